// round 8
// baseline (speedup 1.0000x reference)
#include <cuda_runtime.h>
#include <math.h>

#define NEXP    8
#define HDIM    4096
#define TOK     4
#define WARPS   16
#define THREADS 512
#define NTOK    16384            // 4 * 4096 tokens
#define NGROUP  (NTOK / TOK)     // 4096 warp-groups
#define H4      (HDIM / 4)       // 1024 float4 per row
#define KITERS  (H4 / 32)        // 32 k-iterations per group

typedef unsigned long long u64;

// ---- packed f32x2 helpers (K-adjacent packing: zero mov overhead) ----
__device__ __forceinline__ void fma2(u64& d, u64 a, u64 b) {
    asm("fma.rn.f32x2 %0, %1, %2, %0;" : "+l"(d) : "l"(a), "l"(b));
}
__device__ __forceinline__ float fold2(u64 v) {
    float lo, hi;
    asm("mov.b64 {%0, %1}, %2;" : "=f"(lo), "=f"(hi) : "l"(v));
    return lo + hi;
}
// 16B global load (streaming) as two packed f32x2
__device__ __forceinline__ ulonglong2 ldcs_u2(const void* p) {
    ulonglong2 v;
    asm("ld.global.cs.v2.u64 {%0, %1}, [%2];"
        : "=l"(v.x), "=l"(v.y) : "l"(p));
    return v;
}

__global__ __launch_bounds__(THREADS, 1)
void moe_router_kernel(const float* __restrict__ hs,
                       const float* __restrict__ rw,
                       float* __restrict__ out)
{
    extern __shared__ float sw[];          // [NEXP][HDIM] = 128 KB
    float4* sw4 = reinterpret_cast<float4*>(sw);

    // Stage router weights into shared memory (coalesced, once per block)
    {
        const float4* rw4 = reinterpret_cast<const float4*>(rw);
        #pragma unroll
        for (int i = threadIdx.x; i < NEXP * H4; i += THREADS)
            sw4[i] = rw4[i];
    }
    __syncthreads();

    const int lane  = threadIdx.x & 31;
    const int wid   = threadIdx.x >> 5;
    const int gwarp = blockIdx.x * WARPS + wid;
    const int nwarp = gridDim.x * WARPS;

    const ulonglong2* swu = reinterpret_cast<const ulonglong2*>(sw);

    float* out_w = out;                     // [NTOK, 2] top-k weights
    float* out_i = out + (size_t)NTOK * 2;  // [NTOK, 2] indices (as float)
    float* out_l = out + (size_t)NTOK * 4;  // [NTOK, 8] raw logits

    for (int g = gwarp; g < NGROUP; g += nwarp) {
        const size_t t0 = (size_t)g * TOK;
        const float* hsrow = hs + t0 * HDIM;

        // acc[t][e] = f32x2 {sum over even k-slots, sum over odd k-slots}
        u64 acc[TOK][NEXP];
        #pragma unroll
        for (int t = 0; t < TOK; t++)
            #pragma unroll
            for (int e = 0; e < NEXP; e++)
                acc[t][e] = 0ull;

        // Double-buffered hidden loads (16B each = 2 packed f32x2)
        ulonglong2 hbuf[2][TOK];
        #pragma unroll
        for (int t = 0; t < TOK; t++)
            hbuf[0][t] = ldcs_u2(hsrow + (size_t)t * HDIM + lane * 4);

        #pragma unroll 4
        for (int i = 0; i < KITERS; i++) {
            const int cur = i & 1;

            if (i + 1 < KITERS) {
                const int kf2 = ((i + 1) * 32 + lane) * 4;
                #pragma unroll
                for (int t = 0; t < TOK; t++)
                    hbuf[cur ^ 1][t] = ldcs_u2(hsrow + (size_t)t * HDIM + kf2);
            }

            const int kk = i * 32 + lane;   // float4 index
            ulonglong2 w[NEXP];
            #pragma unroll
            for (int e = 0; e < NEXP; e++)
                w[e] = swu[e * H4 + kk];

            #pragma unroll
            for (int t = 0; t < TOK; t++) {
                const ulonglong2 h = hbuf[cur][t];
                #pragma unroll
                for (int e = 0; e < NEXP; e++) {
                    fma2(acc[t][e], h.x, w[e].x);
                    fma2(acc[t][e], h.y, w[e].y);
                }
            }
        }

        // Fold f32x2 accumulators -> scalar partials v[t*8+e]
        float v[TOK * NEXP];
        #pragma unroll
        for (int t = 0; t < TOK; t++)
            #pragma unroll
            for (int e = 0; e < NEXP; e++)
                v[t * NEXP + e] = fold2(acc[t][e]);

        // Tree-exchange reduction: 31 SHFL; lane L ends with value index L
        #pragma unroll
        for (int o = 16; o >= 1; o >>= 1) {
            const bool up = (lane & o) != 0;
            #pragma unroll
            for (int j = 0; j < o; j++) {
                const float give = up ? v[j] : v[j + o];
                const float keep = up ? v[j + o] : v[j];
                const float recv = __shfl_xor_sync(0xffffffffu, give, o);
                v[j] = keep + recv;
            }
        }

        const float logit = v[0];       // logit[token = lane>>3][expert = lane&7]
        const int   sub   = lane & 7;

        // Coalesced logit store: 32 consecutive floats per warp
        out_l[t0 * NEXP + lane] = logit;

        // Top-1 within each 8-lane token group (ties -> lowest expert index)
        float bv = logit; int bi = sub;
        #pragma unroll
        for (int o = 4; o >= 1; o >>= 1) {
            const float ov = __shfl_xor_sync(0xffffffffu, bv, o);
            const int   oi = __shfl_xor_sync(0xffffffffu, bi, o);
            if (ov > bv || (ov == bv && oi < bi)) { bv = ov; bi = oi; }
        }
        // Top-2: exclude the winner, reduce again
        float sv = (sub == bi) ? -INFINITY : logit; int si = sub;
        #pragma unroll
        for (int o = 4; o >= 1; o >>= 1) {
            const float ov = __shfl_xor_sync(0xffffffffu, sv, o);
            const int   oi = __shfl_xor_sync(0xffffffffu, si, o);
            if (ov > sv || (ov == sv && oi < si)) { sv = ov; si = oi; }
        }

        if (sub == 0) {
            const size_t tok = t0 + (lane >> 3);
            // renormalized top-2 softmax weights
            const float e2 = __expf(sv - bv);
            const float r  = 1.0f / (1.0f + e2);
            out_w[tok * 2 + 0] = r;
            out_w[tok * 2 + 1] = e2 * r;
            out_i[tok * 2 + 0] = (float)bi;
            out_i[tok * 2 + 1] = (float)si;
        }
    }
}

extern "C" void kernel_launch(void* const* d_in, const int* in_sizes, int n_in,
                              void* d_out, int out_size)
{
    const float* hs = (const float*)d_in[0];   // hidden_states [4,4096,4096] f32
    const float* rw = (const float*)d_in[1];   // router_weight [8,4096] f32
    float* out = (float*)d_out;

    (void)in_sizes; (void)n_in; (void)out_size;

    cudaFuncSetAttribute(moe_router_kernel,
                         cudaFuncAttributeMaxDynamicSharedMemorySize,
                         NEXP * HDIM * (int)sizeof(float));

    moe_router_kernel<<<152, THREADS, NEXP * HDIM * sizeof(float)>>>(hs, rw, out);
}